// round 5
// baseline (speedup 1.0000x reference)
#include <cuda_runtime.h>
#include <cuda_bf16.h>

// Problem shape (fixed by the dataset problem)
#define BB 8
#define DD 8
#define HH 512
#define WW 1024
#define PP (HH * WW)      // 524288 pixels per image
#define KK 5              // instance labels 1..K
#define P2 (PP / 2)       // float2 groups per channel plane

#define DELTA_V 0.5f
#define TWO_DELTA_D 6.0f
#define GAMMA 0.001f

#define NBLK1 55          // pass1: 440 CTAs ~= 3/SM @ <=85 regs
#define NBLK2 111         // pass2: 888 CTAs = 6/SM @ <=42 regs
#define NTHR 256
#define NWARP (NTHR / 32)

// -------- scratch (device globals; zero at module load, re-zeroed by k_final
// so every graph replay sees clean state) --------
__device__ float g_sum[BB][KK][DD];
__device__ float g_cnt[BB][KK];
__device__ float g_val[BB][KK];

__device__ __forceinline__ float warp_sum(float v) {
    #pragma unroll
    for (int o = 16; o > 0; o >>= 1)
        v += __shfl_down_sync(0xffffffffu, v, o);
    return v;
}

// ============ pass 1: per-instance sums + counts ============
// Front-batched loads (MLP ~9) + FFMA-weight accumulation (no FSEL chains).
__global__ __launch_bounds__(NTHR, 3) void k_pass1(const float* __restrict__ emb,
                                                   const int* __restrict__ mask) {
    const int b = blockIdx.y;
    const float2* __restrict__ e0 =
        reinterpret_cast<const float2*>(emb + (size_t)b * DD * PP);
    const int2* __restrict__ m0 =
        reinterpret_cast<const int2*>(mask + (size_t)b * PP);

    float s[KK][DD];
    float cnt[KK];
    #pragma unroll
    for (int k = 0; k < KK; k++) {
        cnt[k] = 0.f;
        #pragma unroll
        for (int d = 0; d < DD; d++) s[k][d] = 0.f;
    }

    const int stride = gridDim.x * blockDim.x;
    for (int i = blockIdx.x * blockDim.x + threadIdx.x; i < P2; i += stride) {
        int2 l2 = m0[i];
        float ea[DD], eb[DD];
        #pragma unroll
        for (int d = 0; d < DD; d++) {
            float2 v = e0[(size_t)d * P2 + i];
            ea[d] = v.x; eb[d] = v.y;
        }
        #pragma unroll
        for (int k = 0; k < KK; k++) {
            float ha = (l2.x == k + 1) ? 1.f : 0.f;
            float hb = (l2.y == k + 1) ? 1.f : 0.f;
            cnt[k] += ha + hb;
            #pragma unroll
            for (int d = 0; d < DD; d++) {
                s[k][d] = fmaf(ha, ea[d], s[k][d]);
                s[k][d] = fmaf(hb, eb[d], s[k][d]);
            }
        }
    }

    // warp tree-reduce all 45 accumulators
    #pragma unroll
    for (int k = 0; k < KK; k++) {
        cnt[k] = warp_sum(cnt[k]);
        #pragma unroll
        for (int d = 0; d < DD; d++) s[k][d] = warp_sum(s[k][d]);
    }

    __shared__ float red[NWARP][KK * DD + KK];
    int w = threadIdx.x >> 5, lane = threadIdx.x & 31;
    if (lane == 0) {
        #pragma unroll
        for (int k = 0; k < KK; k++) {
            #pragma unroll
            for (int d = 0; d < DD; d++) red[w][k * DD + d] = s[k][d];
            red[w][KK * DD + k] = cnt[k];
        }
    }
    __syncthreads();
    int t = threadIdx.x;
    if (t < KK * DD) {
        float tot = 0.f;
        #pragma unroll
        for (int ww = 0; ww < NWARP; ww++) tot += red[ww][t];
        atomicAdd(&g_sum[b][0][0] + t, tot);
    } else if (t < KK * DD + KK) {
        float tot = 0.f;
        #pragma unroll
        for (int ww = 0; ww < NWARP; ww++) tot += red[ww][t];
        atomicAdd(&g_cnt[b][t - KK * DD], tot);
    }
}

// ============ pass 2: variance hinge ============
// Each block derives centers locally from g_sum/g_cnt.
__global__ __launch_bounds__(NTHR, 6) void k_pass2(const float* __restrict__ emb,
                                                   const int* __restrict__ mask) {
    const int b = blockIdx.y;
    __shared__ float sc[KK * DD];   // center rows, 32B apart
    if (threadIdx.x < KK * DD) {
        int k = threadIdx.x / DD, d = threadIdx.x % DD;
        sc[threadIdx.x] = g_sum[b][k][d] / fmaxf(g_cnt[b][k], 1.f);
    }
    __syncthreads();

    const float2* __restrict__ e0 =
        reinterpret_cast<const float2*>(emb + (size_t)b * DD * PP);
    const int2* __restrict__ m0 =
        reinterpret_cast<const int2*>(mask + (size_t)b * PP);

    float val[KK];
    #pragma unroll
    for (int k = 0; k < KK; k++) val[k] = 0.f;

    const int stride = gridDim.x * blockDim.x;
    for (int i = blockIdx.x * blockDim.x + threadIdx.x; i < P2; i += stride) {
        int2 l2 = m0[i];
        float ea[DD], eb[DD];
        #pragma unroll
        for (int d = 0; d < DD; d++) {
            float2 v = e0[(size_t)d * P2 + i];
            ea[d] = v.x; eb[d] = v.y;
        }
        #pragma unroll
        for (int j = 0; j < 2; j++) {
            int lab = (j == 0) ? l2.x : l2.y;
            const float* e = (j == 0) ? ea : eb;
            if (lab > 0) {
                int kidx = lab - 1;
                const float4* crow = reinterpret_cast<const float4*>(&sc[kidx * DD]);
                float4 c0 = crow[0];
                float4 c1 = crow[1];
                float d2 = 0.f;
                float df;
                df = e[0] - c0.x; d2 += df * df;
                df = e[1] - c0.y; d2 += df * df;
                df = e[2] - c0.z; d2 += df * df;
                df = e[3] - c0.w; d2 += df * df;
                df = e[4] - c1.x; d2 += df * df;
                df = e[5] - c1.y; d2 += df * df;
                df = e[6] - c1.z; d2 += df * df;
                df = e[7] - c1.w; d2 += df * df;
                float h = fmaxf(sqrtf(d2) - DELTA_V, 0.f);
                float v = h * h;
                #pragma unroll
                for (int k = 0; k < KK; k++)
                    val[k] += (kidx == k) ? v : 0.f;
            }
        }
    }

    #pragma unroll
    for (int k = 0; k < KK; k++) val[k] = warp_sum(val[k]);

    __shared__ float red[NWARP][KK];
    int w = threadIdx.x >> 5, lane = threadIdx.x & 31;
    if (lane == 0) {
        #pragma unroll
        for (int k = 0; k < KK; k++) red[w][k] = val[k];
    }
    __syncthreads();
    if (threadIdx.x < KK) {
        float tot = 0.f;
        #pragma unroll
        for (int ww = 0; ww < NWARP; ww++) tot += red[ww][threadIdx.x];
        atomicAdd(&g_val[b][threadIdx.x], tot);
    }
}

// ============ finalize: dist/reg losses, batch means, re-zero scratch ============
__global__ void k_final(float* __restrict__ out, int out_size) {
    __shared__ float sh_v[BB], sh_d[BB], sh_r[BB], sh_n[BB];
    int t = threadIdx.x;
    if (t < BB) {
        int b = t;
        float cc[KK][DD];
        bool pres[KK];
        float Nf = 0.f;
        float var_b = 0.f;
        #pragma unroll
        for (int k = 0; k < KK; k++) {
            float c = g_cnt[b][k];
            pres[k] = c > 0.f;
            if (pres[k]) { Nf += 1.f; var_b += g_val[b][k] / c; }
            float inv = 1.f / fmaxf(c, 1.f);
            #pragma unroll
            for (int d = 0; d < DD; d++) cc[k][d] = g_sum[b][k][d] * inv;
        }
        var_b /= fmaxf(Nf, 1.f);
        // pairwise center hinge
        float dist = 0.f;
        #pragma unroll
        for (int i = 0; i < KK; i++) {
            #pragma unroll
            for (int j = i + 1; j < KK; j++) {
                if (pres[i] && pres[j]) {
                    float ds = 0.f;
                    #pragma unroll
                    for (int d = 0; d < DD; d++) {
                        float df = cc[i][d] - cc[j][d];
                        ds += df * df;
                    }
                    float h = fmaxf(TWO_DELTA_D - sqrtf(ds), 0.f);
                    dist += h * h;
                }
            }
        }
        float npairs = Nf * (Nf - 1.f) * 0.5f;
        dist /= (Nf > 1.f) ? npairs : 1.f;
        // reg
        float reg = 0.f;
        #pragma unroll
        for (int k = 0; k < KK; k++) {
            if (pres[k]) {
                float n2 = 0.f;
                #pragma unroll
                for (int d = 0; d < DD; d++) n2 += cc[k][d] * cc[k][d];
                reg += sqrtf(n2);
            }
        }
        reg /= fmaxf(Nf, 1.f);
        sh_v[b] = var_b; sh_d[b] = dist; sh_r[b] = reg; sh_n[b] = Nf;
    }
    __syncthreads();
    if (t == 0) {
        float lv = 0.f, ld = 0.f, lr = 0.f, den = 0.f;
        #pragma unroll
        for (int b = 0; b < BB; b++) {
            float has = (sh_n[b] > 0.f) ? 1.f : 0.f;
            lv += sh_v[b] * has;
            ld += sh_d[b] * has;
            lr += sh_r[b] * has;
            den += has;
        }
        den = fmaxf(den, 1.f);
        lv /= den; ld /= den; lr /= den;
        float total = lv + ld + GAMMA * lr;
        if (out_size > 0) out[0] = total;
        if (out_size > 1) out[1] = lv;
        if (out_size > 2) out[2] = ld;
        if (out_size > 3) out[3] = lr;
    }
    // fill extra poisoned slots deterministically
    for (int i = 4 + t; i < out_size; i += blockDim.x) out[i] = 0.f;
    // re-zero scratch for the next graph replay (state was consumed above)
    __syncthreads();
    float* a = &g_sum[0][0][0];                 // 320
    for (int i = t; i < BB * KK * DD; i += blockDim.x) a[i] = 0.f;
    if (t < BB * KK) { (&g_cnt[0][0])[t] = 0.f; (&g_val[0][0])[t] = 0.f; }
}

extern "C" void kernel_launch(void* const* d_in, const int* in_sizes, int n_in,
                              void* d_out, int out_size) {
    const float* emb = (const float*)d_in[0];
    const int* mask = (const int*)d_in[1];
    float* out = (float*)d_out;
    (void)in_sizes; (void)n_in;

    k_pass1<<<dim3(NBLK1, BB), NTHR>>>(emb, mask);
    k_pass2<<<dim3(NBLK2, BB), NTHR>>>(emb, mask);
    k_final<<<1, 128>>>(out, out_size);
}

// round 7
// speedup vs baseline: 1.2964x; 1.2964x over previous
#include <cuda_runtime.h>
#include <cuda_bf16.h>

// Problem shape (fixed by the dataset problem)
#define BB 8
#define DD 8
#define HH 512
#define WW 1024
#define PP (HH * WW)      // 524288 pixels per image
#define KK 5              // instance labels 1..K
#define P2 (PP / 2)       // float2 groups per channel plane
#define DH 4              // channels per pass1 half

#define DELTA_V 0.5f
#define TWO_DELTA_D 6.0f
#define GAMMA 0.001f

#define NBLK1 46          // pass1: 46*8*2 = 736 CTAs = 5/SM, one wave
#define NBLK2 92          // pass2: 736 CTAs = 5/SM @ 51-reg cap
#define NTHR 256
#define NWARP (NTHR / 32)

// -------- scratch (device globals; zero at module load, re-zeroed by k_final
// so every graph replay sees clean state) --------
__device__ float g_sum[BB][KK][DD];
__device__ float g_cnt[BB][KK];
__device__ float g_val[BB][KK];

__device__ __forceinline__ float warp_sum(float v) {
    #pragma unroll
    for (int o = 16; o > 0; o >>= 1)
        v += __shfl_down_sync(0xffffffffu, v, o);
    return v;
}

// ============ pass 1: per-instance sums + counts ============
// Channel-split: blockIdx.z selects 4 of the 8 channels. Accumulators shrink
// to s[5][4] (20 regs) so the kernel fits 5 CTAs/SM without spilling.
// Front-batched loads (1 int2 + 4 float2) + FFMA-weight accumulation.
__global__ __launch_bounds__(NTHR, 5) void k_pass1(const float* __restrict__ emb,
                                                   const int* __restrict__ mask) {
    const int b = blockIdx.y;
    const int half = blockIdx.z;                   // 0: ch 0-3, 1: ch 4-7
    const float2* __restrict__ e0 =
        reinterpret_cast<const float2*>(emb + ((size_t)b * DD + half * DH) * PP);
    const int2* __restrict__ m0 =
        reinterpret_cast<const int2*>(mask + (size_t)b * PP);

    float s[KK][DH];
    float cnt[KK];
    #pragma unroll
    for (int k = 0; k < KK; k++) {
        cnt[k] = 0.f;
        #pragma unroll
        for (int d = 0; d < DH; d++) s[k][d] = 0.f;
    }

    const int stride = gridDim.x * blockDim.x;
    for (int i = blockIdx.x * blockDim.x + threadIdx.x; i < P2; i += stride) {
        int2 l2 = m0[i];
        float ea[DH], eb[DH];
        #pragma unroll
        for (int d = 0; d < DH; d++) {
            float2 v = e0[(size_t)d * P2 + i];
            ea[d] = v.x; eb[d] = v.y;
        }
        #pragma unroll
        for (int k = 0; k < KK; k++) {
            float ha = (l2.x == k + 1) ? 1.f : 0.f;
            float hb = (l2.y == k + 1) ? 1.f : 0.f;
            cnt[k] += ha + hb;                      // only half==0's cnt is used
            #pragma unroll
            for (int d = 0; d < DH; d++) {
                s[k][d] = fmaf(ha, ea[d], s[k][d]);
                s[k][d] = fmaf(hb, eb[d], s[k][d]);
            }
        }
    }

    // warp tree-reduce 25 accumulators (+5 counts)
    #pragma unroll
    for (int k = 0; k < KK; k++) {
        cnt[k] = warp_sum(cnt[k]);
        #pragma unroll
        for (int d = 0; d < DH; d++) s[k][d] = warp_sum(s[k][d]);
    }

    __shared__ float red[NWARP][KK * DH + KK];
    int w = threadIdx.x >> 5, lane = threadIdx.x & 31;
    if (lane == 0) {
        #pragma unroll
        for (int k = 0; k < KK; k++) {
            #pragma unroll
            for (int d = 0; d < DH; d++) red[w][k * DH + d] = s[k][d];
            red[w][KK * DH + k] = cnt[k];
        }
    }
    __syncthreads();
    int t = threadIdx.x;
    if (t < KK * DH) {
        float tot = 0.f;
        #pragma unroll
        for (int ww = 0; ww < NWARP; ww++) tot += red[ww][t];
        int k = t / DH, d = t % DH;
        atomicAdd(&g_sum[b][k][half * DH + d], tot);
    } else if (t < KK * DH + KK && half == 0) {     // counts once (from z=0)
        float tot = 0.f;
        #pragma unroll
        for (int ww = 0; ww < NWARP; ww++) tot += red[ww][t];
        atomicAdd(&g_cnt[b][t - KK * DH], tot);
    }
}

// ============ pass 2: variance hinge ============
// Each block derives centers locally from g_sum/g_cnt.
__global__ __launch_bounds__(NTHR, 5) void k_pass2(const float* __restrict__ emb,
                                                   const int* __restrict__ mask) {
    const int b = blockIdx.y;
    __shared__ float sc[KK * DD];   // center rows, 32B apart
    if (threadIdx.x < KK * DD) {
        int k = threadIdx.x / DD, d = threadIdx.x % DD;
        sc[threadIdx.x] = g_sum[b][k][d] / fmaxf(g_cnt[b][k], 1.f);
    }
    __syncthreads();

    const float2* __restrict__ e0 =
        reinterpret_cast<const float2*>(emb + (size_t)b * DD * PP);
    const int2* __restrict__ m0 =
        reinterpret_cast<const int2*>(mask + (size_t)b * PP);

    float val[KK];
    #pragma unroll
    for (int k = 0; k < KK; k++) val[k] = 0.f;

    const int stride = gridDim.x * blockDim.x;
    for (int i = blockIdx.x * blockDim.x + threadIdx.x; i < P2; i += stride) {
        int2 l2 = m0[i];
        float ea[DD], eb[DD];
        #pragma unroll
        for (int d = 0; d < DD; d++) {
            float2 v = e0[(size_t)d * P2 + i];
            ea[d] = v.x; eb[d] = v.y;
        }
        #pragma unroll
        for (int j = 0; j < 2; j++) {
            int lab = (j == 0) ? l2.x : l2.y;
            const float* e = (j == 0) ? ea : eb;
            if (lab > 0) {
                int kidx = lab - 1;
                const float4* crow = reinterpret_cast<const float4*>(&sc[kidx * DD]);
                float4 c0 = crow[0];
                float4 c1 = crow[1];
                float d2 = 0.f;
                float df;
                df = e[0] - c0.x; d2 += df * df;
                df = e[1] - c0.y; d2 += df * df;
                df = e[2] - c0.z; d2 += df * df;
                df = e[3] - c0.w; d2 += df * df;
                df = e[4] - c1.x; d2 += df * df;
                df = e[5] - c1.y; d2 += df * df;
                df = e[6] - c1.z; d2 += df * df;
                df = e[7] - c1.w; d2 += df * df;
                float h = fmaxf(sqrtf(d2) - DELTA_V, 0.f);
                float v = h * h;
                #pragma unroll
                for (int k = 0; k < KK; k++)
                    val[k] += (kidx == k) ? v : 0.f;
            }
        }
    }

    #pragma unroll
    for (int k = 0; k < KK; k++) val[k] = warp_sum(val[k]);

    __shared__ float red[NWARP][KK];
    int w = threadIdx.x >> 5, lane = threadIdx.x & 31;
    if (lane == 0) {
        #pragma unroll
        for (int k = 0; k < KK; k++) red[w][k] = val[k];
    }
    __syncthreads();
    if (threadIdx.x < KK) {
        float tot = 0.f;
        #pragma unroll
        for (int ww = 0; ww < NWARP; ww++) tot += red[ww][threadIdx.x];
        atomicAdd(&g_val[b][threadIdx.x], tot);
    }
}

// ============ finalize: dist/reg losses, batch means, re-zero scratch ============
__global__ void k_final(float* __restrict__ out, int out_size) {
    __shared__ float sh_v[BB], sh_d[BB], sh_r[BB], sh_n[BB];
    int t = threadIdx.x;
    if (t < BB) {
        int b = t;
        float cc[KK][DD];
        bool pres[KK];
        float Nf = 0.f;
        float var_b = 0.f;
        #pragma unroll
        for (int k = 0; k < KK; k++) {
            float c = g_cnt[b][k];
            pres[k] = c > 0.f;
            if (pres[k]) { Nf += 1.f; var_b += g_val[b][k] / c; }
            float inv = 1.f / fmaxf(c, 1.f);
            #pragma unroll
            for (int d = 0; d < DD; d++) cc[k][d] = g_sum[b][k][d] * inv;
        }
        var_b /= fmaxf(Nf, 1.f);
        // pairwise center hinge
        float dist = 0.f;
        #pragma unroll
        for (int i = 0; i < KK; i++) {
            #pragma unroll
            for (int j = i + 1; j < KK; j++) {
                if (pres[i] && pres[j]) {
                    float ds = 0.f;
                    #pragma unroll
                    for (int d = 0; d < DD; d++) {
                        float df = cc[i][d] - cc[j][d];
                        ds += df * df;
                    }
                    float h = fmaxf(TWO_DELTA_D - sqrtf(ds), 0.f);
                    dist += h * h;
                }
            }
        }
        float npairs = Nf * (Nf - 1.f) * 0.5f;
        dist /= (Nf > 1.f) ? npairs : 1.f;
        // reg
        float reg = 0.f;
        #pragma unroll
        for (int k = 0; k < KK; k++) {
            if (pres[k]) {
                float n2 = 0.f;
                #pragma unroll
                for (int d = 0; d < DD; d++) n2 += cc[k][d] * cc[k][d];
                reg += sqrtf(n2);
            }
        }
        reg /= fmaxf(Nf, 1.f);
        sh_v[b] = var_b; sh_d[b] = dist; sh_r[b] = reg; sh_n[b] = Nf;
    }
    __syncthreads();
    if (t == 0) {
        float lv = 0.f, ld = 0.f, lr = 0.f, den = 0.f;
        #pragma unroll
        for (int b = 0; b < BB; b++) {
            float has = (sh_n[b] > 0.f) ? 1.f : 0.f;
            lv += sh_v[b] * has;
            ld += sh_d[b] * has;
            lr += sh_r[b] * has;
            den += has;
        }
        den = fmaxf(den, 1.f);
        lv /= den; ld /= den; lr /= den;
        float total = lv + ld + GAMMA * lr;
        if (out_size > 0) out[0] = total;
        if (out_size > 1) out[1] = lv;
        if (out_size > 2) out[2] = ld;
        if (out_size > 3) out[3] = lr;
    }
    // fill extra poisoned slots deterministically
    for (int i = 4 + t; i < out_size; i += blockDim.x) out[i] = 0.f;
    // re-zero scratch for the next graph replay (state was consumed above)
    __syncthreads();
    float* a = &g_sum[0][0][0];                 // 320
    for (int i = t; i < BB * KK * DD; i += blockDim.x) a[i] = 0.f;
    if (t < BB * KK) { (&g_cnt[0][0])[t] = 0.f; (&g_val[0][0])[t] = 0.f; }
}

extern "C" void kernel_launch(void* const* d_in, const int* in_sizes, int n_in,
                              void* d_out, int out_size) {
    const float* emb = (const float*)d_in[0];
    const int* mask = (const int*)d_in[1];
    float* out = (float*)d_out;
    (void)in_sizes; (void)n_in;

    k_pass1<<<dim3(NBLK1, BB, 2), NTHR>>>(emb, mask);
    k_pass2<<<dim3(NBLK2, BB), NTHR>>>(emb, mask);
    k_final<<<1, 128>>>(out, out_size);
}

// round 8
// speedup vs baseline: 1.3349x; 1.0297x over previous
#include <cuda_runtime.h>
#include <cuda_bf16.h>

// Problem shape (fixed by the dataset problem)
#define BB 8
#define DD 8
#define HH 512
#define WW 1024
#define PP (HH * WW)      // 524288 pixels per image
#define KK 5              // instance labels 1..K
#define P2 (PP / 2)       // float2 groups per channel plane
#define P4 (PP / 4)       // float4 groups per channel plane
#define DH 4              // channels per pass1 half

#define DELTA_V 0.5f
#define TWO_DELTA_D 6.0f
#define GAMMA 0.001f

#define NBLK1 37          // pass1: 37*8*2 = 592 CTAs = 4/SM, one wave
#define NBLK2 92          // pass2: 736 CTAs = 5/SM @ 51-reg cap
#define NTHR 256
#define NWARP (NTHR / 32)

// -------- scratch (device globals; zero at module load, re-zeroed by k_final
// so every graph replay sees clean state) --------
__device__ float g_sum[BB][KK][DD];
__device__ float g_cnt[BB][KK];
__device__ float g_val[BB][KK];

__device__ __forceinline__ float warp_sum(float v) {
    #pragma unroll
    for (int o = 16; o > 0; o >>= 1)
        v += __shfl_down_sync(0xffffffffu, v, o);
    return v;
}

// ============ pass 1: per-instance sums + counts ============
// Channel-split (blockIdx.z picks 4 of 8 channels) + float4 loads (4 px/iter):
// 5 x 16B loads front-batched -> 2.5 KB outstanding per warp, s[5][4] keeps the
// live set ~53 regs so (256,4) does not spill.
__global__ __launch_bounds__(NTHR, 4) void k_pass1(const float* __restrict__ emb,
                                                   const int* __restrict__ mask) {
    const int b = blockIdx.y;
    const int half = blockIdx.z;                   // 0: ch 0-3, 1: ch 4-7
    const float4* __restrict__ e0 =
        reinterpret_cast<const float4*>(emb + ((size_t)b * DD + half * DH) * PP);
    const int4* __restrict__ m0 =
        reinterpret_cast<const int4*>(mask + (size_t)b * PP);

    float s[KK][DH];
    float cnt[KK];
    #pragma unroll
    for (int k = 0; k < KK; k++) {
        cnt[k] = 0.f;
        #pragma unroll
        for (int d = 0; d < DH; d++) s[k][d] = 0.f;
    }

    const int stride = gridDim.x * blockDim.x;
    for (int i = blockIdx.x * blockDim.x + threadIdx.x; i < P4; i += stride) {
        int4 l = m0[i];
        float4 v[DH];
        #pragma unroll
        for (int d = 0; d < DH; d++) v[d] = e0[(size_t)d * P4 + i];
        #pragma unroll
        for (int k = 0; k < KK; k++) {
            float h0 = (l.x == k + 1) ? 1.f : 0.f;
            float h1 = (l.y == k + 1) ? 1.f : 0.f;
            float h2 = (l.z == k + 1) ? 1.f : 0.f;
            float h3 = (l.w == k + 1) ? 1.f : 0.f;
            cnt[k] += (h0 + h1) + (h2 + h3);
            #pragma unroll
            for (int d = 0; d < DH; d++) {
                s[k][d] = fmaf(h0, v[d].x, s[k][d]);
                s[k][d] = fmaf(h1, v[d].y, s[k][d]);
                s[k][d] = fmaf(h2, v[d].z, s[k][d]);
                s[k][d] = fmaf(h3, v[d].w, s[k][d]);
            }
        }
    }

    // warp tree-reduce 25 accumulators (+5 counts)
    #pragma unroll
    for (int k = 0; k < KK; k++) {
        cnt[k] = warp_sum(cnt[k]);
        #pragma unroll
        for (int d = 0; d < DH; d++) s[k][d] = warp_sum(s[k][d]);
    }

    __shared__ float red[NWARP][KK * DH + KK];
    int w = threadIdx.x >> 5, lane = threadIdx.x & 31;
    if (lane == 0) {
        #pragma unroll
        for (int k = 0; k < KK; k++) {
            #pragma unroll
            for (int d = 0; d < DH; d++) red[w][k * DH + d] = s[k][d];
            red[w][KK * DH + k] = cnt[k];
        }
    }
    __syncthreads();
    int t = threadIdx.x;
    if (t < KK * DH) {
        float tot = 0.f;
        #pragma unroll
        for (int ww = 0; ww < NWARP; ww++) tot += red[ww][t];
        int k = t / DH, d = t % DH;
        atomicAdd(&g_sum[b][k][half * DH + d], tot);
    } else if (t < KK * DH + KK && half == 0) {     // counts once (from z=0)
        float tot = 0.f;
        #pragma unroll
        for (int ww = 0; ww < NWARP; ww++) tot += red[ww][t];
        atomicAdd(&g_cnt[b][t - KK * DH], tot);
    }
}

// ============ pass 2: variance hinge ============
// Each block derives centers locally from g_sum/g_cnt.
__global__ __launch_bounds__(NTHR, 5) void k_pass2(const float* __restrict__ emb,
                                                   const int* __restrict__ mask) {
    const int b = blockIdx.y;
    __shared__ float sc[KK * DD];   // center rows, 32B apart
    if (threadIdx.x < KK * DD) {
        int k = threadIdx.x / DD, d = threadIdx.x % DD;
        sc[threadIdx.x] = g_sum[b][k][d] / fmaxf(g_cnt[b][k], 1.f);
    }
    __syncthreads();

    const float2* __restrict__ e0 =
        reinterpret_cast<const float2*>(emb + (size_t)b * DD * PP);
    const int2* __restrict__ m0 =
        reinterpret_cast<const int2*>(mask + (size_t)b * PP);

    float val[KK];
    #pragma unroll
    for (int k = 0; k < KK; k++) val[k] = 0.f;

    const int stride = gridDim.x * blockDim.x;
    for (int i = blockIdx.x * blockDim.x + threadIdx.x; i < P2; i += stride) {
        int2 l2 = m0[i];
        float ea[DD], eb[DD];
        #pragma unroll
        for (int d = 0; d < DD; d++) {
            float2 v = e0[(size_t)d * P2 + i];
            ea[d] = v.x; eb[d] = v.y;
        }
        #pragma unroll
        for (int j = 0; j < 2; j++) {
            int lab = (j == 0) ? l2.x : l2.y;
            const float* e = (j == 0) ? ea : eb;
            if (lab > 0) {
                int kidx = lab - 1;
                const float4* crow = reinterpret_cast<const float4*>(&sc[kidx * DD]);
                float4 c0 = crow[0];
                float4 c1 = crow[1];
                float d2 = 0.f;
                float df;
                df = e[0] - c0.x; d2 += df * df;
                df = e[1] - c0.y; d2 += df * df;
                df = e[2] - c0.z; d2 += df * df;
                df = e[3] - c0.w; d2 += df * df;
                df = e[4] - c1.x; d2 += df * df;
                df = e[5] - c1.y; d2 += df * df;
                df = e[6] - c1.z; d2 += df * df;
                df = e[7] - c1.w; d2 += df * df;
                float h = fmaxf(sqrtf(d2) - DELTA_V, 0.f);
                float v = h * h;
                #pragma unroll
                for (int k = 0; k < KK; k++)
                    val[k] += (kidx == k) ? v : 0.f;
            }
        }
    }

    #pragma unroll
    for (int k = 0; k < KK; k++) val[k] = warp_sum(val[k]);

    __shared__ float red[NWARP][KK];
    int w = threadIdx.x >> 5, lane = threadIdx.x & 31;
    if (lane == 0) {
        #pragma unroll
        for (int k = 0; k < KK; k++) red[w][k] = val[k];
    }
    __syncthreads();
    if (threadIdx.x < KK) {
        float tot = 0.f;
        #pragma unroll
        for (int ww = 0; ww < NWARP; ww++) tot += red[ww][threadIdx.x];
        atomicAdd(&g_val[b][threadIdx.x], tot);
    }
}

// ============ finalize: dist/reg losses, batch means, re-zero scratch ============
__global__ void k_final(float* __restrict__ out, int out_size) {
    __shared__ float sh_v[BB], sh_d[BB], sh_r[BB], sh_n[BB];
    int t = threadIdx.x;
    if (t < BB) {
        int b = t;
        float cc[KK][DD];
        bool pres[KK];
        float Nf = 0.f;
        float var_b = 0.f;
        #pragma unroll
        for (int k = 0; k < KK; k++) {
            float c = g_cnt[b][k];
            pres[k] = c > 0.f;
            if (pres[k]) { Nf += 1.f; var_b += g_val[b][k] / c; }
            float inv = 1.f / fmaxf(c, 1.f);
            #pragma unroll
            for (int d = 0; d < DD; d++) cc[k][d] = g_sum[b][k][d] * inv;
        }
        var_b /= fmaxf(Nf, 1.f);
        // pairwise center hinge
        float dist = 0.f;
        #pragma unroll
        for (int i = 0; i < KK; i++) {
            #pragma unroll
            for (int j = i + 1; j < KK; j++) {
                if (pres[i] && pres[j]) {
                    float ds = 0.f;
                    #pragma unroll
                    for (int d = 0; d < DD; d++) {
                        float df = cc[i][d] - cc[j][d];
                        ds += df * df;
                    }
                    float h = fmaxf(TWO_DELTA_D - sqrtf(ds), 0.f);
                    dist += h * h;
                }
            }
        }
        float npairs = Nf * (Nf - 1.f) * 0.5f;
        dist /= (Nf > 1.f) ? npairs : 1.f;
        // reg
        float reg = 0.f;
        #pragma unroll
        for (int k = 0; k < KK; k++) {
            if (pres[k]) {
                float n2 = 0.f;
                #pragma unroll
                for (int d = 0; d < DD; d++) n2 += cc[k][d] * cc[k][d];
                reg += sqrtf(n2);
            }
        }
        reg /= fmaxf(Nf, 1.f);
        sh_v[b] = var_b; sh_d[b] = dist; sh_r[b] = reg; sh_n[b] = Nf;
    }
    __syncthreads();
    if (t == 0) {
        float lv = 0.f, ld = 0.f, lr = 0.f, den = 0.f;
        #pragma unroll
        for (int b = 0; b < BB; b++) {
            float has = (sh_n[b] > 0.f) ? 1.f : 0.f;
            lv += sh_v[b] * has;
            ld += sh_d[b] * has;
            lr += sh_r[b] * has;
            den += has;
        }
        den = fmaxf(den, 1.f);
        lv /= den; ld /= den; lr /= den;
        float total = lv + ld + GAMMA * lr;
        if (out_size > 0) out[0] = total;
        if (out_size > 1) out[1] = lv;
        if (out_size > 2) out[2] = ld;
        if (out_size > 3) out[3] = lr;
    }
    // fill extra poisoned slots deterministically
    for (int i = 4 + t; i < out_size; i += blockDim.x) out[i] = 0.f;
    // re-zero scratch for the next graph replay (state was consumed above)
    __syncthreads();
    float* a = &g_sum[0][0][0];                 // 320
    for (int i = t; i < BB * KK * DD; i += blockDim.x) a[i] = 0.f;
    if (t < BB * KK) { (&g_cnt[0][0])[t] = 0.f; (&g_val[0][0])[t] = 0.f; }
}

extern "C" void kernel_launch(void* const* d_in, const int* in_sizes, int n_in,
                              void* d_out, int out_size) {
    const float* emb = (const float*)d_in[0];
    const int* mask = (const int*)d_in[1];
    float* out = (float*)d_out;
    (void)in_sizes; (void)n_in;

    k_pass1<<<dim3(NBLK1, BB, 2), NTHR>>>(emb, mask);
    k_pass2<<<dim3(NBLK2, BB), NTHR>>>(emb, mask);
    k_final<<<1, 128>>>(out, out_size);
}

// round 9
// speedup vs baseline: 1.3385x; 1.0027x over previous
#include <cuda_runtime.h>
#include <cuda_bf16.h>

// Problem shape (fixed by the dataset problem)
#define BB 8
#define DD 8
#define HH 512
#define WW 1024
#define PP (HH * WW)      // 524288 pixels per image
#define KK 5              // instance labels 1..K
#define P4 (PP / 4)       // float4 groups per channel plane
#define DH 4              // channels per pass1 half

#define DELTA_V 0.5f
#define TWO_DELTA_D 6.0f
#define GAMMA 0.001f

#define NBLK1 37          // pass1: 37*8*2 = 592 CTAs = 4/SM, one wave
#define NBLK2 74          // pass2: 592 CTAs = 4/SM
#define NTHR 256
#define NWARP (NTHR / 32)

// -------- scratch (device globals; zero at module load, re-zeroed by k_final
// so every graph replay sees clean state) --------
__device__ float g_sum[BB][KK][DD];
__device__ float g_cnt[BB][KK];
__device__ float g_val1[BB];       // pass2: pre-divided variance sum per batch

__device__ __forceinline__ float warp_sum(float v) {
    #pragma unroll
    for (int o = 16; o > 0; o >>= 1)
        v += __shfl_down_sync(0xffffffffu, v, o);
    return v;
}

// ============ pass 1: per-instance sums + counts ============
// Channel-split (blockIdx.z picks 4 of 8 channels), float4 loads (4 px/iter),
// predicated packed-f32x2 accumulation: per (k,px) = 1 setp + 2 @p add.f32x2
// + 1 @p add.s32 instead of 2 sel-ops + 4 FFMA. Identical add order/semantics.
__global__ __launch_bounds__(NTHR, 4) void k_pass1(const float* __restrict__ emb,
                                                   const int* __restrict__ mask) {
    const int b = blockIdx.y;
    const int half = blockIdx.z;                   // 0: ch 0-3, 1: ch 4-7
    const float4* __restrict__ e0 =
        reinterpret_cast<const float4*>(emb + ((size_t)b * DD + half * DH) * PP);
    const int4* __restrict__ m0 =
        reinterpret_cast<const int4*>(mask + (size_t)b * PP);

    unsigned long long s01[KK], s23[KK];  // packed {ch d, ch d+1} fp32 pairs
    int cnti[KK];
    #pragma unroll
    for (int k = 0; k < KK; k++) { s01[k] = 0ull; s23[k] = 0ull; cnti[k] = 0; }

    const int stride = gridDim.x * blockDim.x;
    for (int i = blockIdx.x * blockDim.x + threadIdx.x; i < P4; i += stride) {
        int4 l = m0[i];
        float4 v0 = e0[0 * (size_t)P4 + i];
        float4 v1 = e0[1 * (size_t)P4 + i];
        float4 v2 = e0[2 * (size_t)P4 + i];
        float4 v3 = e0[3 * (size_t)P4 + i];
        #pragma unroll
        for (int j = 0; j < 4; j++) {
            int lab = (j == 0) ? l.x : (j == 1) ? l.y : (j == 2) ? l.z : l.w;
            float a0 = (j == 0) ? v0.x : (j == 1) ? v0.y : (j == 2) ? v0.z : v0.w;
            float a1 = (j == 0) ? v1.x : (j == 1) ? v1.y : (j == 2) ? v1.z : v1.w;
            float a2 = (j == 0) ? v2.x : (j == 1) ? v2.y : (j == 2) ? v2.z : v2.w;
            float a3 = (j == 0) ? v3.x : (j == 1) ? v3.y : (j == 2) ? v3.z : v3.w;
            unsigned long long p01, p23;
            asm("mov.b64 %0, {%1,%2};" : "=l"(p01) : "f"(a0), "f"(a1));
            asm("mov.b64 %0, {%1,%2};" : "=l"(p23) : "f"(a2), "f"(a3));
            #pragma unroll
            for (int k = 0; k < KK; k++) {
                asm("{\n\t"
                    ".reg .pred p;\n\t"
                    "setp.eq.s32 p, %3, %4;\n\t"
                    "@p add.rn.f32x2 %0, %0, %5;\n\t"
                    "@p add.rn.f32x2 %1, %1, %6;\n\t"
                    "@p add.s32 %2, %2, 1;\n\t"
                    "}"
                    : "+l"(s01[k]), "+l"(s23[k]), "+r"(cnti[k])
                    : "r"(lab), "r"(k + 1), "l"(p01), "l"(p23));
            }
        }
    }

    // unpack and reduce 25 accumulators (+5 counts)
    float s[KK][DH];
    float cnt[KK];
    #pragma unroll
    for (int k = 0; k < KK; k++) {
        asm("mov.b64 {%0,%1}, %2;" : "=f"(s[k][0]), "=f"(s[k][1]) : "l"(s01[k]));
        asm("mov.b64 {%0,%1}, %2;" : "=f"(s[k][2]), "=f"(s[k][3]) : "l"(s23[k]));
        cnt[k] = (float)cnti[k];
    }
    #pragma unroll
    for (int k = 0; k < KK; k++) {
        cnt[k] = warp_sum(cnt[k]);
        #pragma unroll
        for (int d = 0; d < DH; d++) s[k][d] = warp_sum(s[k][d]);
    }

    __shared__ float red[NWARP][KK * DH + KK];
    int w = threadIdx.x >> 5, lane = threadIdx.x & 31;
    if (lane == 0) {
        #pragma unroll
        for (int k = 0; k < KK; k++) {
            #pragma unroll
            for (int d = 0; d < DH; d++) red[w][k * DH + d] = s[k][d];
            red[w][KK * DH + k] = cnt[k];
        }
    }
    __syncthreads();
    int t = threadIdx.x;
    if (t < KK * DH) {
        float tot = 0.f;
        #pragma unroll
        for (int ww = 0; ww < NWARP; ww++) tot += red[ww][t];
        int k = t / DH, d = t % DH;
        atomicAdd(&g_sum[b][k][half * DH + d], tot);
    } else if (t < KK * DH + KK && half == 0) {     // counts once (from z=0)
        float tot = 0.f;
        #pragma unroll
        for (int ww = 0; ww < NWARP; ww++) tot += red[ww][t];
        atomicAdd(&g_cnt[b][t - KK * DH], tot);
    }
}

// ============ pass 2: variance hinge ============
// float4 loads (4 px/iter). Per-instance divide folded into the pixel loop via
// inv_cnt stored in the padded smem center row -> ONE scalar accumulator.
__global__ __launch_bounds__(NTHR, 4) void k_pass2(const float* __restrict__ emb,
                                                   const int* __restrict__ mask) {
    const int b = blockIdx.y;
    __shared__ float sc[KK * 12];   // per k: c[0..7], inv_cnt at +8, pad to 12
    if (threadIdx.x < KK) {
        int k = threadIdx.x;
        float c = g_cnt[b][k];
        float inv = 1.f / fmaxf(c, 1.f);
        #pragma unroll
        for (int d = 0; d < DD; d++) sc[k * 12 + d] = g_sum[b][k][d] * inv;
        sc[k * 12 + 8] = inv;
    }
    __syncthreads();

    const float4* __restrict__ e0 =
        reinterpret_cast<const float4*>(emb + (size_t)b * DD * PP);
    const int4* __restrict__ m0 =
        reinterpret_cast<const int4*>(mask + (size_t)b * PP);

    float val = 0.f;

    const int stride = gridDim.x * blockDim.x;
    for (int i = blockIdx.x * blockDim.x + threadIdx.x; i < P4; i += stride) {
        int4 l = m0[i];
        float4 e[DD];
        #pragma unroll
        for (int d = 0; d < DD; d++) e[d] = e0[(size_t)d * P4 + i];
        #pragma unroll
        for (int j = 0; j < 4; j++) {
            int lab = (j == 0) ? l.x : (j == 1) ? l.y : (j == 2) ? l.z : l.w;
            if (lab > 0) {
                const float* row = &sc[(lab - 1) * 12];
                float4 c0 = *reinterpret_cast<const float4*>(row);
                float4 c1 = *reinterpret_cast<const float4*>(row + 4);
                float invc = row[8];
                float d2 = 0.f, df;
                #define EC(d) ((j == 0) ? e[d].x : (j == 1) ? e[d].y : (j == 2) ? e[d].z : e[d].w)
                df = EC(0) - c0.x; d2 += df * df;
                df = EC(1) - c0.y; d2 += df * df;
                df = EC(2) - c0.z; d2 += df * df;
                df = EC(3) - c0.w; d2 += df * df;
                df = EC(4) - c1.x; d2 += df * df;
                df = EC(5) - c1.y; d2 += df * df;
                df = EC(6) - c1.z; d2 += df * df;
                df = EC(7) - c1.w; d2 += df * df;
                #undef EC
                float h = fmaxf(sqrtf(d2) - DELTA_V, 0.f);
                val = fmaf(h * h, invc, val);
            }
        }
    }

    val = warp_sum(val);

    __shared__ float red[NWARP];
    int w = threadIdx.x >> 5, lane = threadIdx.x & 31;
    if (lane == 0) red[w] = val;
    __syncthreads();
    if (threadIdx.x == 0) {
        float tot = 0.f;
        #pragma unroll
        for (int ww = 0; ww < NWARP; ww++) tot += red[ww];
        atomicAdd(&g_val1[b], tot);
    }
}

// ============ finalize: dist/reg losses, batch means, re-zero scratch ============
__global__ void k_final(float* __restrict__ out, int out_size) {
    __shared__ float sh_v[BB], sh_d[BB], sh_r[BB], sh_n[BB];
    int t = threadIdx.x;
    if (t < BB) {
        int b = t;
        float cc[KK][DD];
        bool pres[KK];
        float Nf = 0.f;
        #pragma unroll
        for (int k = 0; k < KK; k++) {
            float c = g_cnt[b][k];
            pres[k] = c > 0.f;
            if (pres[k]) Nf += 1.f;
            float inv = 1.f / fmaxf(c, 1.f);
            #pragma unroll
            for (int d = 0; d < DD; d++) cc[k][d] = g_sum[b][k][d] * inv;
        }
        float var_b = g_val1[b] / fmaxf(Nf, 1.f);
        // pairwise center hinge
        float dist = 0.f;
        #pragma unroll
        for (int i = 0; i < KK; i++) {
            #pragma unroll
            for (int j = i + 1; j < KK; j++) {
                if (pres[i] && pres[j]) {
                    float ds = 0.f;
                    #pragma unroll
                    for (int d = 0; d < DD; d++) {
                        float df = cc[i][d] - cc[j][d];
                        ds += df * df;
                    }
                    float h = fmaxf(TWO_DELTA_D - sqrtf(ds), 0.f);
                    dist += h * h;
                }
            }
        }
        float npairs = Nf * (Nf - 1.f) * 0.5f;
        dist /= (Nf > 1.f) ? npairs : 1.f;
        // reg
        float reg = 0.f;
        #pragma unroll
        for (int k = 0; k < KK; k++) {
            if (pres[k]) {
                float n2 = 0.f;
                #pragma unroll
                for (int d = 0; d < DD; d++) n2 += cc[k][d] * cc[k][d];
                reg += sqrtf(n2);
            }
        }
        reg /= fmaxf(Nf, 1.f);
        sh_v[b] = var_b; sh_d[b] = dist; sh_r[b] = reg; sh_n[b] = Nf;
    }
    __syncthreads();
    if (t == 0) {
        float lv = 0.f, ld = 0.f, lr = 0.f, den = 0.f;
        #pragma unroll
        for (int b = 0; b < BB; b++) {
            float has = (sh_n[b] > 0.f) ? 1.f : 0.f;
            lv += sh_v[b] * has;
            ld += sh_d[b] * has;
            lr += sh_r[b] * has;
            den += has;
        }
        den = fmaxf(den, 1.f);
        lv /= den; ld /= den; lr /= den;
        float total = lv + ld + GAMMA * lr;
        if (out_size > 0) out[0] = total;
        if (out_size > 1) out[1] = lv;
        if (out_size > 2) out[2] = ld;
        if (out_size > 3) out[3] = lr;
    }
    // fill extra poisoned slots deterministically
    for (int i = 4 + t; i < out_size; i += blockDim.x) out[i] = 0.f;
    // re-zero scratch for the next graph replay (state was consumed above)
    __syncthreads();
    float* a = &g_sum[0][0][0];                 // 320
    for (int i = t; i < BB * KK * DD; i += blockDim.x) a[i] = 0.f;
    if (t < BB * KK) (&g_cnt[0][0])[t] = 0.f;
    if (t < BB) g_val1[t] = 0.f;
}

extern "C" void kernel_launch(void* const* d_in, const int* in_sizes, int n_in,
                              void* d_out, int out_size) {
    const float* emb = (const float*)d_in[0];
    const int* mask = (const int*)d_in[1];
    float* out = (float*)d_out;
    (void)in_sizes; (void)n_in;

    k_pass1<<<dim3(NBLK1, BB, 2), NTHR>>>(emb, mask);
    k_pass2<<<dim3(NBLK2, BB), NTHR>>>(emb, mask);
    k_final<<<1, 128>>>(out, out_size);
}

// round 11
// speedup vs baseline: 1.6231x; 1.2126x over previous
#include <cuda_runtime.h>
#include <cuda_bf16.h>

// Problem shape (fixed by the dataset problem)
#define BB 8
#define DD 8
#define HH 512
#define WW 1024
#define PP (HH * WW)      // 524288 pixels per image
#define KK 5              // instance labels 1..K
#define P4 (PP / 4)       // float4 groups per channel plane
#define DH 4              // channels per pass1 half

#define DELTA_V 0.5f
#define TWO_DELTA_D 6.0f
#define GAMMA 0.001f

#define NBLK1 37          // pass1: 37*8*2 = 592 CTAs = 4/SM, one wave
#define NBLK2 74          // pass2: 592 CTAs = 4/SM
#define NTHR 256
#define NWARP (NTHR / 32)

// -------- scratch (device globals; zero at module load, re-zeroed by k_final
// so every graph replay sees clean state) --------
__device__ float g_sum[BB][KK][DD];
__device__ float g_cnt[BB][KK];
__device__ float g_val1[BB];       // pass2: pre-divided variance sum per batch

__device__ __forceinline__ float warp_sum(float v) {
    #pragma unroll
    for (int o = 16; o > 0; o >>= 1)
        v += __shfl_down_sync(0xffffffffu, v, o);
    return v;
}

// ============ pass 1: per-instance sums + counts ============
// Channel-split (blockIdx.z picks 4 of 8 channels) + float4 loads (4 px/iter),
// select+FFMA accumulation (round-8 proven form).
__global__ __launch_bounds__(NTHR, 4) void k_pass1(const float* __restrict__ emb,
                                                   const int* __restrict__ mask) {
    const int b = blockIdx.y;
    const int half = blockIdx.z;                   // 0: ch 0-3, 1: ch 4-7
    const float4* __restrict__ e0 =
        reinterpret_cast<const float4*>(emb + ((size_t)b * DD + half * DH) * PP);
    const int4* __restrict__ m0 =
        reinterpret_cast<const int4*>(mask + (size_t)b * PP);

    float s[KK][DH];
    float cnt[KK];
    #pragma unroll
    for (int k = 0; k < KK; k++) {
        cnt[k] = 0.f;
        #pragma unroll
        for (int d = 0; d < DH; d++) s[k][d] = 0.f;
    }

    const int stride = gridDim.x * blockDim.x;
    for (int i = blockIdx.x * blockDim.x + threadIdx.x; i < P4; i += stride) {
        int4 l = m0[i];
        float4 v[DH];
        #pragma unroll
        for (int d = 0; d < DH; d++) v[d] = e0[(size_t)d * P4 + i];
        #pragma unroll
        for (int k = 0; k < KK; k++) {
            float h0 = (l.x == k + 1) ? 1.f : 0.f;
            float h1 = (l.y == k + 1) ? 1.f : 0.f;
            float h2 = (l.z == k + 1) ? 1.f : 0.f;
            float h3 = (l.w == k + 1) ? 1.f : 0.f;
            cnt[k] += (h0 + h1) + (h2 + h3);
            #pragma unroll
            for (int d = 0; d < DH; d++) {
                s[k][d] = fmaf(h0, v[d].x, s[k][d]);
                s[k][d] = fmaf(h1, v[d].y, s[k][d]);
                s[k][d] = fmaf(h2, v[d].z, s[k][d]);
                s[k][d] = fmaf(h3, v[d].w, s[k][d]);
            }
        }
    }

    // warp tree-reduce 25 accumulators (+5 counts)
    #pragma unroll
    for (int k = 0; k < KK; k++) {
        cnt[k] = warp_sum(cnt[k]);
        #pragma unroll
        for (int d = 0; d < DH; d++) s[k][d] = warp_sum(s[k][d]);
    }

    __shared__ float red[NWARP][KK * DH + KK];
    int w = threadIdx.x >> 5, lane = threadIdx.x & 31;
    if (lane == 0) {
        #pragma unroll
        for (int k = 0; k < KK; k++) {
            #pragma unroll
            for (int d = 0; d < DH; d++) red[w][k * DH + d] = s[k][d];
            red[w][KK * DH + k] = cnt[k];
        }
    }
    __syncthreads();
    int t = threadIdx.x;
    if (t < KK * DH) {
        float tot = 0.f;
        #pragma unroll
        for (int ww = 0; ww < NWARP; ww++) tot += red[ww][t];
        int k = t / DH, d = t % DH;
        atomicAdd(&g_sum[b][k][half * DH + d], tot);
    } else if (t < KK * DH + KK && half == 0) {     // counts once (from z=0)
        float tot = 0.f;
        #pragma unroll
        for (int ww = 0; ww < NWARP; ww++) tot += red[ww][t];
        atomicAdd(&g_cnt[b][t - KK * DH], tot);
    }
}

// ============ pass 2: variance hinge ============
// float4 loads (4 px/iter), DESCENDING traversal: the kernel boundary acts as
// a grid barrier, and L2 (126MB) persists across launches — reading the tail
// of pass1's 144MB stream first converts a large fraction of pass2's reads
// into L2 hits. Per-instance divide folded into the loop via inv_cnt in smem.
__global__ __launch_bounds__(NTHR, 4) void k_pass2(const float* __restrict__ emb,
                                                   const int* __restrict__ mask) {
    const int b = blockIdx.y;
    __shared__ float sc[KK * 12];   // per k: c[0..7], inv_cnt at +8, pad to 12
    if (threadIdx.x < KK) {
        int k = threadIdx.x;
        float c = g_cnt[b][k];
        float inv = 1.f / fmaxf(c, 1.f);
        #pragma unroll
        for (int d = 0; d < DD; d++) sc[k * 12 + d] = g_sum[b][k][d] * inv;
        sc[k * 12 + 8] = inv;
    }
    __syncthreads();

    const float4* __restrict__ e0 =
        reinterpret_cast<const float4*>(emb + (size_t)b * DD * PP);
    const int4* __restrict__ m0 =
        reinterpret_cast<const int4*>(mask + (size_t)b * PP);

    float val = 0.f;

    const int stride = gridDim.x * blockDim.x;
    for (int i = P4 - 1 - (int)(blockIdx.x * blockDim.x + threadIdx.x);
         i >= 0; i -= stride) {
        int4 l = m0[i];
        float4 e[DD];
        #pragma unroll
        for (int d = 0; d < DD; d++) e[d] = e0[(size_t)d * P4 + i];
        #pragma unroll
        for (int j = 0; j < 4; j++) {
            int lab = (j == 0) ? l.x : (j == 1) ? l.y : (j == 2) ? l.z : l.w;
            if (lab > 0) {
                const float* row = &sc[(lab - 1) * 12];
                float4 c0 = *reinterpret_cast<const float4*>(row);
                float4 c1 = *reinterpret_cast<const float4*>(row + 4);
                float invc = row[8];
                float d2 = 0.f, df;
                #define EC(d) ((j == 0) ? e[d].x : (j == 1) ? e[d].y : (j == 2) ? e[d].z : e[d].w)
                df = EC(0) - c0.x; d2 += df * df;
                df = EC(1) - c0.y; d2 += df * df;
                df = EC(2) - c0.z; d2 += df * df;
                df = EC(3) - c0.w; d2 += df * df;
                df = EC(4) - c1.x; d2 += df * df;
                df = EC(5) - c1.y; d2 += df * df;
                df = EC(6) - c1.z; d2 += df * df;
                df = EC(7) - c1.w; d2 += df * df;
                #undef EC
                float h = fmaxf(sqrtf(d2) - DELTA_V, 0.f);
                val = fmaf(h * h, invc, val);
            }
        }
    }

    val = warp_sum(val);

    __shared__ float red[NWARP];
    int w = threadIdx.x >> 5, lane = threadIdx.x & 31;
    if (lane == 0) red[w] = val;
    __syncthreads();
    if (threadIdx.x == 0) {
        float tot = 0.f;
        #pragma unroll
        for (int ww = 0; ww < NWARP; ww++) tot += red[ww];
        atomicAdd(&g_val1[b], tot);
    }
}

// ============ finalize: dist/reg losses, batch means, re-zero scratch ============
__global__ void k_final(float* __restrict__ out, int out_size) {
    __shared__ float sh_v[BB], sh_d[BB], sh_r[BB], sh_n[BB];
    int t = threadIdx.x;
    if (t < BB) {
        int b = t;
        float cc[KK][DD];
        bool pres[KK];
        float Nf = 0.f;
        #pragma unroll
        for (int k = 0; k < KK; k++) {
            float c = g_cnt[b][k];
            pres[k] = c > 0.f;
            if (pres[k]) Nf += 1.f;
            float inv = 1.f / fmaxf(c, 1.f);
            #pragma unroll
            for (int d = 0; d < DD; d++) cc[k][d] = g_sum[b][k][d] * inv;
        }
        float var_b = g_val1[b] / fmaxf(Nf, 1.f);
        // pairwise center hinge
        float dist = 0.f;
        #pragma unroll
        for (int i = 0; i < KK; i++) {
            #pragma unroll
            for (int j = i + 1; j < KK; j++) {
                if (pres[i] && pres[j]) {
                    float ds = 0.f;
                    #pragma unroll
                    for (int d = 0; d < DD; d++) {
                        float df = cc[i][d] - cc[j][d];
                        ds += df * df;
                    }
                    float h = fmaxf(TWO_DELTA_D - sqrtf(ds), 0.f);
                    dist += h * h;
                }
            }
        }
        float npairs = Nf * (Nf - 1.f) * 0.5f;
        dist /= (Nf > 1.f) ? npairs : 1.f;
        // reg
        float reg = 0.f;
        #pragma unroll
        for (int k = 0; k < KK; k++) {
            if (pres[k]) {
                float n2 = 0.f;
                #pragma unroll
                for (int d = 0; d < DD; d++) n2 += cc[k][d] * cc[k][d];
                reg += sqrtf(n2);
            }
        }
        reg /= fmaxf(Nf, 1.f);
        sh_v[b] = var_b; sh_d[b] = dist; sh_r[b] = reg; sh_n[b] = Nf;
    }
    __syncthreads();
    if (t == 0) {
        float lv = 0.f, ld = 0.f, lr = 0.f, den = 0.f;
        #pragma unroll
        for (int b = 0; b < BB; b++) {
            float has = (sh_n[b] > 0.f) ? 1.f : 0.f;
            lv += sh_v[b] * has;
            ld += sh_d[b] * has;
            lr += sh_r[b] * has;
            den += has;
        }
        den = fmaxf(den, 1.f);
        lv /= den; ld /= den; lr /= den;
        float total = lv + ld + GAMMA * lr;
        if (out_size > 0) out[0] = total;
        if (out_size > 1) out[1] = lv;
        if (out_size > 2) out[2] = ld;
        if (out_size > 3) out[3] = lr;
    }
    // fill extra poisoned slots deterministically
    for (int i = 4 + t; i < out_size; i += blockDim.x) out[i] = 0.f;
    // re-zero scratch for the next graph replay (state was consumed above)
    __syncthreads();
    float* a = &g_sum[0][0][0];                 // 320
    for (int i = t; i < BB * KK * DD; i += blockDim.x) a[i] = 0.f;
    if (t < BB * KK) (&g_cnt[0][0])[t] = 0.f;
    if (t < BB) g_val1[t] = 0.f;
}

extern "C" void kernel_launch(void* const* d_in, const int* in_sizes, int n_in,
                              void* d_out, int out_size) {
    const float* emb = (const float*)d_in[0];
    const int* mask = (const int*)d_in[1];
    float* out = (float*)d_out;
    (void)in_sizes; (void)n_in;

    k_pass1<<<dim3(NBLK1, BB, 2), NTHR>>>(emb, mask);
    k_pass2<<<dim3(NBLK2, BB), NTHR>>>(emb, mask);
    k_final<<<1, 128>>>(out, out_size);
}